// round 4
// baseline (speedup 1.0000x reference)
#include <cuda_runtime.h>
#include <math.h>

#define NANCH   8400
#define MAXB    32
#define NCLS    80
#define MAXDET  100
#define NBKT    1024
#define CCAP    256      // chunk capacity (= NMS sort width = blockDim)

// ---------------- device scratch (static zero-init; self-cleaning across graph replays) ----------------
__device__ float  g_scores[MAXB * NANCH];
__device__ float4 g_boxes [MAXB * NANCH];
__device__ int    g_labels[MAXB * NANCH];
__device__ int    g_maxabs[MAXB];          // float bits (non-negative), atomicMax
__device__ int    g_hist  [MAXB][NBKT];    // per-image score histogram

__device__ __forceinline__ float sigmoidf_(float x) {
    return 1.0f / (1.0f + expf(-x));
}

// ---------------- decode: 4 anchors/thread + histogram + boxmax fused ----------------
__global__ void __launch_bounds__(256) k_decode(
    const float* __restrict__ cls0, const float* __restrict__ reg0, const float* __restrict__ obj0,
    const float* __restrict__ cls1, const float* __restrict__ reg1, const float* __restrict__ obj1,
    const float* __restrict__ cls2, const float* __restrict__ reg2, const float* __restrict__ obj2)
{
    const int b = blockIdx.y;
    const int a = (blockIdx.x * blockDim.x + threadIdx.x) * 4;
    float m4 = 0.0f;

    if (a < NANCH) {
        const float *cls, *reg, *obj;
        int a0, w, hw; float s;
        if (a < 6400)      { cls = cls0; reg = reg0; obj = obj0; a0 = a;        w = 80; hw = 6400; s = 8.0f;  }
        else if (a < 8000) { cls = cls1; reg = reg1; obj = obj1; a0 = a - 6400; w = 40; hw = 1600; s = 16.0f; }
        else               { cls = cls2; reg = reg2; obj = obj2; a0 = a - 8000; w = 20; hw = 400;  s = 32.0f; }

        const int hw4 = hw >> 2;
        const int q   = a0 >> 2;

        const float4* c4 = (const float4*)(cls + (size_t)b * NCLS * hw) + q;
        float4 v = c4[0];
        float m0 = v.x, m1 = v.y, m2 = v.z, m3 = v.w;
        int   l0 = 0,   l1 = 0,   l2 = 0,   l3 = 0;
        #pragma unroll 4
        for (int c = 1; c < NCLS; ++c) {
            v = c4[(size_t)c * hw4];
            if (v.x > m0) { m0 = v.x; l0 = c; }
            if (v.y > m1) { m1 = v.y; l1 = c; }
            if (v.z > m2) { m2 = v.z; l2 = c; }
            if (v.w > m3) { m3 = v.w; l3 = c; }
        }

        float4 ov = *((const float4*)(obj + (size_t)b * hw) + q);
        const float* rb = reg + (size_t)b * 4 * hw;
        float4 r0 = *((const float4*)(rb)          + q);
        float4 r1 = *((const float4*)(rb +     hw) + q);
        float4 r2 = *((const float4*)(rb + 2 * hw) + q);
        float4 r3 = *((const float4*)(rb + 3 * hw) + q);

        float mm[4] = { m0, m1, m2, m3 };
        int   ll[4] = { l0, l1, l2, l3 };
        float oo[4] = { ov.x, ov.y, ov.z, ov.w };
        float rx[4] = { r0.x, r0.y, r0.z, r0.w };
        float ry[4] = { r1.x, r1.y, r1.z, r1.w };
        float rw[4] = { r2.x, r2.y, r2.z, r2.w };
        float rh[4] = { r3.x, r3.y, r3.z, r3.w };

        const size_t base = (size_t)b * NANCH + a;
        float sc[4];
        #pragma unroll
        for (int i = 0; i < 4; ++i) {
            sc[i] = __fmul_rn(sigmoidf_(mm[i]), sigmoidf_(oo[i]));
            int ai = a0 + i;
            float px = (float)(ai % w) * s;
            float py = (float)(ai / w) * s;
            float cx = __fadd_rn(__fmul_rn(rx[i], s), px);
            float cy = __fadd_rn(__fmul_rn(ry[i], s), py);
            float bw = __fmul_rn(expf(rw[i]), s);
            float bh = __fmul_rn(expf(rh[i]), s);
            float hx = __fmul_rn(bw, 0.5f);
            float hy = __fmul_rn(bh, 0.5f);
            float x1 = __fsub_rn(cx, hx), y1 = __fsub_rn(cy, hy);
            float x2 = __fadd_rn(cx, hx), y2 = __fadd_rn(cy, hy);
            g_boxes[base + i] = make_float4(x1, y1, x2, y2);
            m4 = fmaxf(m4, fmaxf(fmaxf(fabsf(x1), fabsf(y1)), fmaxf(fabsf(x2), fabsf(y2))));
            if (sc[i] >= 0.01f) {
                int bkt = (int)(sc[i] * 1024.0f);
                if (bkt > NBKT - 1) bkt = NBKT - 1;
                atomicAdd(&g_hist[b][bkt], 1);
            }
        }
        *((float4*)(g_scores + base)) = make_float4(sc[0], sc[1], sc[2], sc[3]);
        *((int4*)(g_labels + base))   = make_int4(ll[0], ll[1], ll[2], ll[3]);
    }

    #pragma unroll
    for (int o = 16; o > 0; o >>= 1)
        m4 = fmaxf(m4, __shfl_xor_sync(0xFFFFFFFFu, m4, o));
    if ((threadIdx.x & 31) == 0 && m4 > 0.0f)
        atomicMax(&g_maxabs[b], __float_as_int(m4));
}

__device__ __forceinline__ unsigned long long shflx64(unsigned long long v, int j) {
    return __shfl_xor_sync(0xFFFFFFFFu, v, j);
}

// exact reference IoU>thr test (a = earlier/kept box, bx = candidate), offset boxes
__device__ __forceinline__ bool iou_gt(float4 a, float4 bx) {
    float tlx = fmaxf(a.x, bx.x), tly = fmaxf(a.y, bx.y);
    float brx = fminf(a.z, bx.z), bry = fminf(a.w, bx.w);
    float ww = fmaxf(__fsub_rn(brx, tlx), 0.0f);
    float hh = fmaxf(__fsub_rn(bry, tly), 0.0f);
    float inter = __fmul_rn(ww, hh);
    float a1 = __fmul_rn(__fsub_rn(a.z, a.x), __fsub_rn(a.w, a.y));
    float a2 = __fmul_rn(__fsub_rn(bx.z, bx.x), __fsub_rn(bx.w, bx.y));
    float den = __fadd_rn(__fsub_rn(__fadd_rn(a1, a2), inter), 1e-6f);
    return __fdiv_rn(inter, den) > 0.65f;
}

// ---------------- NMS: compact -> sort -> ballot column matrix -> register-mask greedy ----------------
__global__ void __launch_bounds__(256) k_nms(float* __restrict__ out, int B)
{
    __shared__ int                s_hist[NBKT];
    __shared__ unsigned long long s_key[CCAP];
    __shared__ float4             s_box[CCAP];
    __shared__ unsigned           s_col[CCAP][8];     // col[j]: later candidates j suppresses
    __shared__ int                s_predead[CCAP];
    __shared__ float4             s_keptb[MAXDET];
    __shared__ int                s_kepti[MAXDET];
    __shared__ float              s_off;
    __shared__ int                s_cnt, s_kc, s_lo, s_hi, s_ptr;

    const int b    = blockIdx.x;
    const int tid  = threadIdx.x;
    const int wid  = tid >> 5;
    const int lane = tid & 31;
    const size_t base = (size_t)b * NANCH;

    #pragma unroll
    for (int k = tid; k < NBKT; k += 256) {
        s_hist[k] = g_hist[b][k];
        g_hist[b][k] = 0;
    }
    if (tid == 0) {
        s_off = __fadd_rn(__int_as_float(g_maxabs[b]), 1.0f);
        g_maxabs[b] = 0;
        s_ptr = NBKT - 1;
        s_kc = 0;
    }
    __syncthreads();
    const float off = s_off;

    for (;;) {
        __syncthreads();
        if (s_kc >= MAXDET || s_ptr < 0) break;

        if (tid == 0) {
            int acc = 0;
            int hi = s_ptr, p = hi;
            while (p >= 0) {
                int h = s_hist[p];
                if (acc > 0 && acc + h > CCAP) break;
                acc += h; --p;
                if (acc >= CCAP) break;
            }
            s_lo = p + 1; s_hi = hi; s_ptr = p; s_cnt = 0;
        }
        __syncthreads();
        const int lo = s_lo, hi = s_hi;

        // compact: one vectorized sweep over scores (L2-resident)
        for (int i4 = tid; i4 < NANCH / 4; i4 += 256) {
            float4 s4 = *((const float4*)(g_scores + base) + i4);
            float sv[4] = { s4.x, s4.y, s4.z, s4.w };
            #pragma unroll
            for (int k = 0; k < 4; ++k) {
                float scv = sv[k];
                if (scv >= 0.01f) {
                    int bkt = (int)(scv * 1024.0f);
                    if (bkt > NBKT - 1) bkt = NBKT - 1;
                    if (bkt >= lo && bkt <= hi) {
                        int p = atomicAdd(&s_cnt, 1);
                        if (p < CCAP) {
                            unsigned u = __float_as_uint(scv);
                            u = ~(u ^ 0x80000000u);
                            s_key[p] = ((unsigned long long)u << 32) | (unsigned)(i4 * 4 + k);
                        }
                    }
                }
            }
        }
        __syncthreads();
        int cN = s_cnt; if (cN > CCAP) cN = CCAP;
        if (tid >= cN) s_key[tid] = 0xFFFFFFFFFFFFFFFFull;
        __syncthreads();

        // ---- bitonic sort 256 keys ascending (= score desc, idx asc) ----
        {
            unsigned long long v = s_key[tid];
            #pragma unroll
            for (int k = 2; k <= 32; k <<= 1) {
                bool up = ((tid & k) == 0);
                #pragma unroll
                for (int j = k >> 1; j > 0; j >>= 1) {
                    unsigned long long p = shflx64(v, j);
                    bool keepSmall = (((tid & j) == 0) == up);
                    if (keepSmall ? (p < v) : (p > v)) v = p;
                }
            }
            s_key[tid] = v;
            __syncthreads();
        }
        #pragma unroll
        for (int k = 64; k <= CCAP; k <<= 1) {
            for (int j = k >> 1; j >= 32; j >>= 1) {
                int i = tid, l = i ^ j;
                if (l > i) {
                    unsigned long long A = s_key[i], Bv = s_key[l];
                    bool up = ((i & k) == 0);
                    if ((A > Bv) == up) { s_key[i] = Bv; s_key[l] = A; }
                }
                __syncthreads();
            }
            {
                unsigned long long v = s_key[tid];
                bool up = ((tid & k) == 0);
                #pragma unroll
                for (int j = 16; j > 0; j >>= 1) {
                    unsigned long long p = shflx64(v, j);
                    bool keepSmall = (((tid & j) == 0) == up);
                    if (keepSmall ? (p < v) : (p > v)) v = p;
                }
                s_key[tid] = v;
                __syncthreads();
            }
        }

        // ---- gather shifted boxes; predead vs previously-kept (usually kc0 == 0) ----
        const int kc0 = s_kc;
        {
            int dead = 0;
            if (tid < cN) {
                int idx = (int)(s_key[tid] & 0xFFFFFFFFull);
                float4 mybox = g_boxes[base + idx];
                float t = __fmul_rn((float)g_labels[base + idx], off);
                mybox.x = __fadd_rn(mybox.x, t);
                mybox.y = __fadd_rn(mybox.y, t);
                mybox.z = __fadd_rn(mybox.z, t);
                mybox.w = __fadd_rn(mybox.w, t);
                s_box[tid] = mybox;
                for (int j2 = 0; j2 < kc0; ++j2)
                    if (iou_gt(s_keptb[j2], mybox)) { dead = 1; break; }
            }
            s_predead[tid] = dead;
        }
        __syncthreads();

        // ---- suppression columns via warp ballots (pipelined, no serial chains) ----
        // warp handles suppressor j (uniform across lanes); lanes cover candidates c.
        for (int j = wid; j < cN; j += 8) {
            float4 bj = s_box[j];
            const int w0 = j >> 5;
            #pragma unroll
            for (int w = 0; w < 8; ++w) {
                unsigned res = 0u;
                if (w >= w0) {
                    int c = (w << 5) + lane;
                    float4 bc = s_box[c];       // stale beyond cN -> masked below
                    bool sup = (c > j) && (c < cN) && iou_gt(bj, bc);
                    res = __ballot_sync(0xFFFFFFFFu, sup);
                }
                if (lane == 0) s_col[j][w] = res;
            }
        }
        __syncthreads();

        // ---- greedy: 256-bit dead mask in registers, single warp (all lanes redundant) ----
        if (tid < 32) {
            unsigned D[8];
            #pragma unroll
            for (int w = 0; w < 8; ++w)
                D[w] = __ballot_sync(0xFFFFFFFFu, s_predead[(w << 5) + lane] != 0);

            int kc = kc0;
            #pragma unroll
            for (int w = 0; w < 8; ++w) {
                int cbase = w << 5;
                if (cbase >= cN || kc >= MAXDET) break;
                #pragma unroll 4
                for (int bi = 0; bi < 32; ++bi) {
                    int c = cbase + bi;
                    if (c >= cN || kc >= MAXDET) break;
                    if (!((D[w] >> bi) & 1u)) {
                        const uint4* cp = (const uint4*)&s_col[c][0];
                        uint4 c0 = cp[0], c1 = cp[1];
                        D[0] |= c0.x; D[1] |= c0.y; D[2] |= c0.z; D[3] |= c0.w;
                        D[4] |= c1.x; D[5] |= c1.y; D[6] |= c1.z; D[7] |= c1.w;
                        if (lane == 0) {
                            s_keptb[kc] = s_box[c];
                            s_kepti[kc] = (int)(s_key[c] & 0xFFFFFFFFull);
                        }
                        ++kc;
                    }
                }
            }
            if (lane == 0) s_kc = kc;
        }
    }
    __syncthreads();

    // ---- outputs: boxes | scores | labels | valid ----
    int kc = s_kc;
    float* ob  = out;
    float* osc = out + (size_t)B * MAXDET * 4;
    float* olb = osc + (size_t)B * MAXDET;
    float* ovl = olb + (size_t)B * MAXDET;

    if (tid < MAXDET) {
        int r = tid;
        float4 bx = make_float4(0.f, 0.f, 0.f, 0.f);
        float scv = 0.f, lb = -1.f, vl = 0.f;
        if (r < kc) {
            int idx = s_kepti[r];
            bx = g_boxes[base + idx];
            scv = g_scores[base + idx];
            lb = (float)g_labels[base + idx];
            vl = 1.0f;
        }
        float* obp = ob + ((size_t)b * MAXDET + r) * 4;
        obp[0] = bx.x; obp[1] = bx.y; obp[2] = bx.z; obp[3] = bx.w;
        osc[(size_t)b * MAXDET + r] = scv;
        olb[(size_t)b * MAXDET + r] = lb;
        ovl[(size_t)b * MAXDET + r] = vl;
    }
}

// ---------------- launch ----------------
extern "C" void kernel_launch(void* const* d_in, const int* in_sizes, int n_in,
                              void* d_out, int out_size)
{
    int B = in_sizes[0] / 512000;
    if (B < 1) B = 1;
    if (B > MAXB) B = MAXB;

    const float *cls[3], *reg[3], *obj[3];
    bool grouped = (n_in >= 9) && (in_sizes[1] == B * 128000);
    if (grouped) {
        for (int i = 0; i < 3; ++i) {
            cls[i] = (const float*)d_in[i];
            reg[i] = (const float*)d_in[3 + i];
            obj[i] = (const float*)d_in[6 + i];
        }
    } else {
        for (int i = 0; i < 3; ++i) {
            cls[i] = (const float*)d_in[3 * i];
            reg[i] = (const float*)d_in[3 * i + 1];
            obj[i] = (const float*)d_in[3 * i + 2];
        }
    }

    dim3 g1((NANCH / 4 + 255) / 256, B);
    k_decode<<<g1, 256>>>(cls[0], reg[0], obj[0],
                          cls[1], reg[1], obj[1],
                          cls[2], reg[2], obj[2]);
    k_nms<<<B, 256>>>((float*)d_out, B);
}

// round 5
// speedup vs baseline: 1.2761x; 1.2761x over previous
#include <cuda_runtime.h>
#include <math.h>

#define NANCH   8400
#define MAXB    32
#define NCLS    80
#define MAXDET  100
#define NBKT    1024
#define CCAP    256      // chunk capacity (= NMS sort width = blockDim)

// ---------------- device scratch (static zero-init; self-cleaning across graph replays) ----------------
__device__ float  g_scores[MAXB * NANCH];
__device__ float4 g_boxes [MAXB * NANCH];
__device__ int    g_labels[MAXB * NANCH];
__device__ int    g_maxabs[MAXB];          // float bits (non-negative), atomicMax
__device__ int    g_hist  [MAXB][NBKT];    // per-image score histogram

__device__ __forceinline__ float sigmoidf_(float x) {
    return 1.0f / (1.0f + expf(-x));
}

// ---------------- decode: 4 anchors/thread + histogram + boxmax fused (at memory roofline) ----------------
__global__ void __launch_bounds__(256) k_decode(
    const float* __restrict__ cls0, const float* __restrict__ reg0, const float* __restrict__ obj0,
    const float* __restrict__ cls1, const float* __restrict__ reg1, const float* __restrict__ obj1,
    const float* __restrict__ cls2, const float* __restrict__ reg2, const float* __restrict__ obj2)
{
    const int b = blockIdx.y;
    const int a = (blockIdx.x * blockDim.x + threadIdx.x) * 4;
    float m4 = 0.0f;

    if (a < NANCH) {
        const float *cls, *reg, *obj;
        int a0, w, hw; float s;
        if (a < 6400)      { cls = cls0; reg = reg0; obj = obj0; a0 = a;        w = 80; hw = 6400; s = 8.0f;  }
        else if (a < 8000) { cls = cls1; reg = reg1; obj = obj1; a0 = a - 6400; w = 40; hw = 1600; s = 16.0f; }
        else               { cls = cls2; reg = reg2; obj = obj2; a0 = a - 8000; w = 20; hw = 400;  s = 32.0f; }

        const int hw4 = hw >> 2;
        const int q   = a0 >> 2;

        const float4* c4 = (const float4*)(cls + (size_t)b * NCLS * hw) + q;
        float4 v = c4[0];
        float m0 = v.x, m1 = v.y, m2 = v.z, m3 = v.w;
        int   l0 = 0,   l1 = 0,   l2 = 0,   l3 = 0;
        #pragma unroll 4
        for (int c = 1; c < NCLS; ++c) {
            v = c4[(size_t)c * hw4];
            if (v.x > m0) { m0 = v.x; l0 = c; }
            if (v.y > m1) { m1 = v.y; l1 = c; }
            if (v.z > m2) { m2 = v.z; l2 = c; }
            if (v.w > m3) { m3 = v.w; l3 = c; }
        }

        float4 ov = *((const float4*)(obj + (size_t)b * hw) + q);
        const float* rb = reg + (size_t)b * 4 * hw;
        float4 r0 = *((const float4*)(rb)          + q);
        float4 r1 = *((const float4*)(rb +     hw) + q);
        float4 r2 = *((const float4*)(rb + 2 * hw) + q);
        float4 r3 = *((const float4*)(rb + 3 * hw) + q);

        float mm[4] = { m0, m1, m2, m3 };
        int   ll[4] = { l0, l1, l2, l3 };
        float oo[4] = { ov.x, ov.y, ov.z, ov.w };
        float rx[4] = { r0.x, r0.y, r0.z, r0.w };
        float ry[4] = { r1.x, r1.y, r1.z, r1.w };
        float rw[4] = { r2.x, r2.y, r2.z, r2.w };
        float rh[4] = { r3.x, r3.y, r3.z, r3.w };

        const size_t base = (size_t)b * NANCH + a;
        float sc[4];
        #pragma unroll
        for (int i = 0; i < 4; ++i) {
            sc[i] = __fmul_rn(sigmoidf_(mm[i]), sigmoidf_(oo[i]));
            int ai = a0 + i;
            float px = (float)(ai % w) * s;
            float py = (float)(ai / w) * s;
            float cx = __fadd_rn(__fmul_rn(rx[i], s), px);
            float cy = __fadd_rn(__fmul_rn(ry[i], s), py);
            float bw = __fmul_rn(expf(rw[i]), s);
            float bh = __fmul_rn(expf(rh[i]), s);
            float hx = __fmul_rn(bw, 0.5f);
            float hy = __fmul_rn(bh, 0.5f);
            float x1 = __fsub_rn(cx, hx), y1 = __fsub_rn(cy, hy);
            float x2 = __fadd_rn(cx, hx), y2 = __fadd_rn(cy, hy);
            g_boxes[base + i] = make_float4(x1, y1, x2, y2);
            m4 = fmaxf(m4, fmaxf(fmaxf(fabsf(x1), fabsf(y1)), fmaxf(fabsf(x2), fabsf(y2))));
            if (sc[i] >= 0.01f) {
                int bkt = (int)(sc[i] * 1024.0f);
                if (bkt > NBKT - 1) bkt = NBKT - 1;
                atomicAdd(&g_hist[b][bkt], 1);
            }
        }
        *((float4*)(g_scores + base)) = make_float4(sc[0], sc[1], sc[2], sc[3]);
        *((int4*)(g_labels + base))   = make_int4(ll[0], ll[1], ll[2], ll[3]);
    }

    #pragma unroll
    for (int o = 16; o > 0; o >>= 1)
        m4 = fmaxf(m4, __shfl_xor_sync(0xFFFFFFFFu, m4, o));
    if ((threadIdx.x & 31) == 0 && m4 > 0.0f)
        atomicMax(&g_maxabs[b], __float_as_int(m4));
}

__device__ __forceinline__ unsigned long long shflx64(unsigned long long v, int j) {
    return __shfl_xor_sync(0xFFFFFFFFu, v, j);
}

// exact reference IoU>thr test on offset boxes (formula symmetric in args)
__device__ __forceinline__ bool iou_gt(float4 a, float4 bx) {
    float tlx = fmaxf(a.x, bx.x), tly = fmaxf(a.y, bx.y);
    float brx = fminf(a.z, bx.z), bry = fminf(a.w, bx.w);
    float ww = fmaxf(__fsub_rn(brx, tlx), 0.0f);
    float hh = fmaxf(__fsub_rn(bry, tly), 0.0f);
    float inter = __fmul_rn(ww, hh);
    float a1 = __fmul_rn(__fsub_rn(a.z, a.x), __fsub_rn(a.w, a.y));
    float a2 = __fmul_rn(__fsub_rn(bx.z, bx.x), __fsub_rn(bx.w, bx.y));
    float den = __fadd_rn(__fsub_rn(__fadd_rn(a1, a2), inter), 1e-6f);
    return __fdiv_rn(inter, den) > 0.65f;
}

// ---------------- NMS: compact -> sort -> sparse same-label rows -> flag-gated greedy ----------------
__global__ void __launch_bounds__(256) k_nms(float* __restrict__ out, int B)
{
    __shared__ int                s_hist[NBKT];
    __shared__ unsigned long long s_key[CCAP];
    __shared__ float4             s_box[CCAP];
    __shared__ unsigned           s_row[CCAP][8];      // row[c]: earlier same-label suppressors of c
    __shared__ unsigned char      s_lab8[CCAP];        // packed labels
    __shared__ unsigned char      s_flags[CCAP];       // bit0: predead, bit1: has suppressor
    __shared__ unsigned char      s_kord[CCAP];        // kept candidate indices (this round)
    __shared__ float4             s_keptb[MAXDET];
    __shared__ unsigned char      s_klab[MAXDET];
    __shared__ int                s_kepti[MAXDET];
    __shared__ float              s_off;
    __shared__ int                s_cnt, s_kc, s_lo, s_hi, s_ptr;

    const int b   = blockIdx.x;
    const int tid = threadIdx.x;
    const size_t base = (size_t)b * NANCH;

    #pragma unroll
    for (int k = tid; k < NBKT; k += 256) {
        s_hist[k] = g_hist[b][k];
        g_hist[b][k] = 0;
    }
    if (tid == 0) {
        s_off = __fadd_rn(__int_as_float(g_maxabs[b]), 1.0f);
        g_maxabs[b] = 0;
        s_ptr = NBKT - 1;
        s_kc = 0;
    }
    __syncthreads();
    const float off = s_off;

    for (;;) {
        __syncthreads();
        if (s_kc >= MAXDET || s_ptr < 0) break;

        if (tid == 0) {
            int acc = 0;
            int hi = s_ptr, p = hi;
            while (p >= 0) {
                int h = s_hist[p];
                if (acc > 0 && acc + h > CCAP) break;
                acc += h; --p;
                if (acc >= CCAP) break;
            }
            s_lo = p + 1; s_hi = hi; s_ptr = p; s_cnt = 0;
        }
        __syncthreads();
        const int lo = s_lo, hi = s_hi;

        // ---- compact: one vectorized sweep over L2-resident scores ----
        for (int i4 = tid; i4 < NANCH / 4; i4 += 256) {
            float4 s4 = *((const float4*)(g_scores + base) + i4);
            float sv[4] = { s4.x, s4.y, s4.z, s4.w };
            #pragma unroll
            for (int k = 0; k < 4; ++k) {
                float scv = sv[k];
                if (scv >= 0.01f) {
                    int bkt = (int)(scv * 1024.0f);
                    if (bkt > NBKT - 1) bkt = NBKT - 1;
                    if (bkt >= lo && bkt <= hi) {
                        int p = atomicAdd(&s_cnt, 1);
                        if (p < CCAP) {
                            unsigned u = __float_as_uint(scv);
                            u = ~(u ^ 0x80000000u);
                            s_key[p] = ((unsigned long long)u << 32) | (unsigned)(i4 * 4 + k);
                        }
                    }
                }
            }
        }
        __syncthreads();
        int cN = s_cnt; if (cN > CCAP) cN = CCAP;
        if (tid >= cN) s_key[tid] = 0xFFFFFFFFFFFFFFFFull;
        __syncthreads();

        // ---- bitonic sort 256 keys ascending (= score desc, idx asc) ----
        {
            unsigned long long v = s_key[tid];
            #pragma unroll
            for (int k = 2; k <= 32; k <<= 1) {
                bool up = ((tid & k) == 0);
                #pragma unroll
                for (int j = k >> 1; j > 0; j >>= 1) {
                    unsigned long long p = shflx64(v, j);
                    bool keepSmall = (((tid & j) == 0) == up);
                    if (keepSmall ? (p < v) : (p > v)) v = p;
                }
            }
            s_key[tid] = v;
            __syncthreads();
        }
        #pragma unroll
        for (int k = 64; k <= CCAP; k <<= 1) {
            for (int j = k >> 1; j >= 32; j >>= 1) {
                int i = tid, l = i ^ j;
                if (l > i) {
                    unsigned long long A = s_key[i], Bv = s_key[l];
                    bool up = ((i & k) == 0);
                    if ((A > Bv) == up) { s_key[i] = Bv; s_key[l] = A; }
                }
                __syncthreads();
            }
            {
                unsigned long long v = s_key[tid];
                bool up = ((tid & k) == 0);
                #pragma unroll
                for (int j = 16; j > 0; j >>= 1) {
                    unsigned long long p = shflx64(v, j);
                    bool keepSmall = (((tid & j) == 0) == up);
                    if (keepSmall ? (p < v) : (p > v)) v = p;
                }
                s_key[tid] = v;
                __syncthreads();
            }
        }

        // ---- gather shifted boxes + labels; predead vs previously-kept; zero rows ----
        const int kc0 = s_kc;
        float4 mybox = make_float4(0.f, 0.f, 0.f, 0.f);
        int    mylab = -1;
        int    pred  = 1;                       // tid >= cN counts as dead
        if (tid < cN) {
            int idx = (int)(s_key[tid] & 0xFFFFFFFFull);
            mybox = g_boxes[base + idx];
            mylab = g_labels[base + idx];
            float t = __fmul_rn((float)mylab, off);
            mybox.x = __fadd_rn(mybox.x, t);
            mybox.y = __fadd_rn(mybox.y, t);
            mybox.z = __fadd_rn(mybox.z, t);
            mybox.w = __fadd_rn(mybox.w, t);
            s_box[tid]  = mybox;
            s_lab8[tid] = (unsigned char)mylab;
            pred = 0;
            for (int j2 = 0; j2 < kc0; ++j2)
                if (s_klab[j2] == (unsigned char)mylab && iou_gt(s_keptb[j2], mybox)) { pred = 1; break; }
        }
        {
            uint4 z = make_uint4(0u, 0u, 0u, 0u);
            ((uint4*)&s_row[tid][0])[0] = z;
            ((uint4*)&s_row[tid][0])[1] = z;
        }
        __syncthreads();

        // ---- sparse suppressor rows: vcmpeq4 label scan, IoU only on same-label hits ----
        {
            unsigned any = 0;
            if (tid < cN && pred == 0) {
                const unsigned* lab4 = (const unsigned*)s_lab8;
                unsigned myl4 = (unsigned)mylab * 0x01010101u;
                int nw4 = tid >> 2;
                for (int jw = 0; jw < nw4; ++jw) {
                    unsigned m = __vcmpeq4(lab4[jw], myl4);
                    if (m != 0u) {
                        #pragma unroll
                        for (int t = 0; t < 4; ++t) {
                            if ((m >> (t * 8)) & 1u) {
                                int j = jw * 4 + t;
                                if (iou_gt(s_box[j], mybox)) {
                                    s_row[tid][j >> 5] |= (1u << (j & 31));
                                    any = 1u;
                                }
                            }
                        }
                    }
                }
                for (int j = nw4 * 4; j < tid; ++j) {
                    if (s_lab8[j] == (unsigned char)mylab && iou_gt(s_box[j], mybox)) {
                        s_row[tid][j >> 5] |= (1u << (j & 31));
                        any = 1u;
                    }
                }
            }
            s_flags[tid] = (unsigned char)(pred | (any << 1));
        }
        __syncthreads();

        // ---- greedy: single thread, flags 4-at-a-time, kept mask in registers ----
        if (tid == 0) {
            unsigned K0=0,K1=0,K2=0,K3=0,K4=0,K5=0,K6=0,K7=0;
            int kc = kc0;
            int nk = 0;                                   // kept this round
            const unsigned* f4 = (const unsigned*)s_flags;
            for (int g = 0; g < CCAP / 4 && kc < MAXDET; ++g) {
                int c0 = g * 4;
                if (c0 >= cN) break;
                unsigned fw = f4[g];
                if (fw == 0u && c0 + 4 <= cN && kc + 4 <= MAXDET) {
                    // 4 unconditional keeps
                    unsigned bits = 0xFu << (c0 & 31);
                    switch (c0 >> 5) {
                        case 0: K0 |= bits; break; case 1: K1 |= bits; break;
                        case 2: K2 |= bits; break; case 3: K3 |= bits; break;
                        case 4: K4 |= bits; break; case 5: K5 |= bits; break;
                        case 6: K6 |= bits; break; default: K7 |= bits; break;
                    }
                    s_kord[nk]   = (unsigned char)(c0);
                    s_kord[nk+1] = (unsigned char)(c0+1);
                    s_kord[nk+2] = (unsigned char)(c0+2);
                    s_kord[nk+3] = (unsigned char)(c0+3);
                    nk += 4; kc += 4;
                    continue;
                }
                #pragma unroll
                for (int t = 0; t < 4; ++t) {
                    int c = c0 + t;
                    if (c >= cN || kc >= MAXDET) break;
                    unsigned fb = (fw >> (t * 8)) & 0xFFu;
                    bool alive;
                    if (fb == 0u) alive = true;
                    else if (fb & 1u) alive = false;
                    else {
                        const uint4* rp = (const uint4*)&s_row[c][0];
                        uint4 r0 = rp[0], r1 = rp[1];
                        alive = ((r0.x & K0) | (r0.y & K1) | (r0.z & K2) | (r0.w & K3) |
                                 (r1.x & K4) | (r1.y & K5) | (r1.z & K6) | (r1.w & K7)) == 0u;
                    }
                    if (alive) {
                        unsigned bit = 1u << (c & 31);
                        switch (c >> 5) {
                            case 0: K0 |= bit; break; case 1: K1 |= bit; break;
                            case 2: K2 |= bit; break; case 3: K3 |= bit; break;
                            case 4: K4 |= bit; break; case 5: K5 |= bit; break;
                            case 6: K6 |= bit; break; default: K7 |= bit; break;
                        }
                        s_kord[nk] = (unsigned char)c;
                        ++nk; ++kc;
                    }
                }
            }
            s_kc = kc;
            s_cnt = nk;     // reuse as kept-this-round count
        }
        __syncthreads();

        // ---- record kept boxes for cross-round predead + output ----
        {
            int nk = s_cnt;
            if (tid < nk) {
                int c = s_kord[tid];
                int slot = kc0 + tid;
                s_keptb[slot] = s_box[c];
                s_klab[slot]  = s_lab8[c];
                s_kepti[slot] = (int)(s_key[c] & 0xFFFFFFFFull);
            }
        }
    }
    __syncthreads();

    // ---- outputs: boxes | scores | labels | valid ----
    int kc = s_kc;
    float* ob  = out;
    float* osc = out + (size_t)B * MAXDET * 4;
    float* olb = osc + (size_t)B * MAXDET;
    float* ovl = olb + (size_t)B * MAXDET;

    if (tid < MAXDET) {
        int r = tid;
        float4 bx = make_float4(0.f, 0.f, 0.f, 0.f);
        float scv = 0.f, lb = -1.f, vl = 0.f;
        if (r < kc) {
            int idx = s_kepti[r];
            bx = g_boxes[base + idx];
            scv = g_scores[base + idx];
            lb = (float)g_labels[base + idx];
            vl = 1.0f;
        }
        float* obp = ob + ((size_t)b * MAXDET + r) * 4;
        obp[0] = bx.x; obp[1] = bx.y; obp[2] = bx.z; obp[3] = bx.w;
        osc[(size_t)b * MAXDET + r] = scv;
        olb[(size_t)b * MAXDET + r] = lb;
        ovl[(size_t)b * MAXDET + r] = vl;
    }
}

// ---------------- launch ----------------
extern "C" void kernel_launch(void* const* d_in, const int* in_sizes, int n_in,
                              void* d_out, int out_size)
{
    int B = in_sizes[0] / 512000;
    if (B < 1) B = 1;
    if (B > MAXB) B = MAXB;

    const float *cls[3], *reg[3], *obj[3];
    bool grouped = (n_in >= 9) && (in_sizes[1] == B * 128000);
    if (grouped) {
        for (int i = 0; i < 3; ++i) {
            cls[i] = (const float*)d_in[i];
            reg[i] = (const float*)d_in[3 + i];
            obj[i] = (const float*)d_in[6 + i];
        }
    } else {
        for (int i = 0; i < 3; ++i) {
            cls[i] = (const float*)d_in[3 * i];
            reg[i] = (const float*)d_in[3 * i + 1];
            obj[i] = (const float*)d_in[3 * i + 2];
        }
    }

    dim3 g1((NANCH / 4 + 255) / 256, B);
    k_decode<<<g1, 256>>>(cls[0], reg[0], obj[0],
                          cls[1], reg[1], obj[1],
                          cls[2], reg[2], obj[2]);
    k_nms<<<B, 256>>>((float*)d_out, B);
}